// round 12
// baseline (speedup 1.0000x reference)
#include <cuda_runtime.h>
#include <cuda_fp16.h>

#define T_LEN 2048
#define E_N   19
#define B_N   64

typedef unsigned int u32;

// final hidden states: [b][e][dir*32+u]
__device__ float g_hfinal[B_N * E_N * 64];

__device__ __forceinline__ float tanh_ap(float x) {
    float r;
    asm("tanh.approx.f32 %0, %1;" : "=f"(r) : "f"(x));
    return r;
}

__device__ __forceinline__ u32 pack_hf2(float lo, float hi) {
    __half2 p;
    p.x = __float2half(lo);    // low 16 bits = lower k index
    p.y = __float2half(hi);
    return *(u32*)&p;
}

// D += A(16x16 fp16, row-major) * B(16x8 fp16, col-major), fp32 accumulate
__device__ __forceinline__ void mma16816(float d[4], const u32 a[4], u32 b0, u32 b1) {
    asm volatile(
        "mma.sync.aligned.m16n8k16.row.col.f32.f16.f16.f32 "
        "{%0,%1,%2,%3}, {%4,%5,%6,%7}, {%8,%9}, {%0,%1,%2,%3};"
        : "+f"(d[0]), "+f"(d[1]), "+f"(d[2]), "+f"(d[3])
        : "r"(a[0]), "r"(a[1]), "r"(a[2]), "r"(a[3]), "r"(b0), "r"(b1));
}

// One CTA = one (e,dir) x (8*NG) batch items, 4 warps, NG independent 8-item
// groups per warp (groups share the A fragments; chains interleave).
// Warp w owns units 8w..8w+7; M-rows permuted [i(8);f(8);g(8);o(8)] so each
// thread holds all four gates for (unit u, items it0/it1) after the MMA.
// h layout pos(u) = ((u&7)>>1)*8 + 2w + (u&1) -> single LDS.128 per group;
// double-buffered bsm; seeds pipelined into previous epilogue via shfl.
template <int NG>
__device__ __forceinline__ void run_lstm(
    const float* __restrict__ x, const float* __restrict__ w_ih,
    const float* __restrict__ w_hh, const float* __restrict__ b_ih,
    const float* __restrict__ b_hh,
    int ed, int b0, int tid, __half (*bsm)[2][8][32])
{
    const int w    = tid >> 5;
    const int lane = tid & 31;
    const int grp  = lane >> 2;
    const int tig  = lane & 3;
    const int e    = ed >> 1;
    const int d    = ed & 1;

    const int u     = 8 * w + grp;
    const int pos_u = (grp >> 1) * 8 + 2 * w + (grp & 1);

    // ---- A fragments: m-tile mt rows = [gate 2mt units; gate 2mt+1 units] ----
    u32 A[2][2][4];
    {
        const float* Wp = w_hh + ed * 128 * 32;
#pragma unroll
        for (int mt = 0; mt < 2; mt++) {
            const int g0 = 2 * mt, g1 = 2 * mt + 1;
            const float C0 = (g0 == 2) ? 1.0f : 0.5f;
            const float C1 = (g1 == 2) ? 1.0f : 0.5f;
            const float* r0 = Wp + (g0 * 32 + u) * 32;
            const float* r1 = Wp + (g1 * 32 + u) * 32;
#pragma unroll
            for (int kt = 0; kt < 2; kt++) {
                const int kb = 16 * kt + 2 * tig;
                A[mt][kt][0] = pack_hf2(r0[kb] * C0,     r0[kb + 1] * C0);
                A[mt][kt][1] = pack_hf2(r1[kb] * C1,     r1[kb + 1] * C1);
                A[mt][kt][2] = pack_hf2(r0[kb + 8] * C0, r0[kb + 9] * C0);
                A[mt][kt][3] = pack_hf2(r1[kb + 8] * C1, r1[kb + 9] * C1);
            }
        }
    }

    // input weight / bias for unit u, gates 0..3 (activation scale folded)
    float wihC[4], biasC[4];
#pragma unroll
    for (int g = 0; g < 4; g++) {
        const float Cg = (g == 2) ? 1.0f : 0.5f;
        const int row = ed * 128 + g * 32 + u;
        wihC[g]  = Cg * w_ih[row];
        biasC[g] = Cg * (b_ih[row] + b_hh[row]);
    }

    // ---- zero both h buffers (h0 = 0): 2*2*8*32 halves = 512 u32 ----
    {
        const int nwords = 2 * 2 * 8 * 32 * (int)sizeof(__half) / 4;   // 512
        for (int i = tid; i < nwords; i += 128) ((u32*)bsm)[i] = 0u;
    }

    // ---- x pipeline: lane owns item (lane&7) + 8*(group of lane) ----
    const int tstart = d ? (T_LEN - 1) : 0;
    const int stride = d ? -E_N : E_N;
    const int myitem = (lane & 7) + 8 * ((lane >> 3) & (NG - 1));
    const float* xp = x + ((long long)(b0 + myitem) * T_LEN + tstart) * E_N + e;
    float xq  = __ldg(xp);
    xp += stride;
    float xqn = __ldg(xp);

    const int it0 = 2 * tig, it1 = 2 * tig + 1;

    // seeds for t=0, per group
    float Dn[NG][2][4];
#pragma unroll
    for (int g = 0; g < NG; g++) {
        const float xv0 = __shfl_sync(0xffffffffu, xq, 8 * g + it0);
        const float xv1 = __shfl_sync(0xffffffffu, xq, 8 * g + it1);
#pragma unroll
        for (int mt = 0; mt < 2; mt++) {
            Dn[g][mt][0] = fmaf(xv0, wihC[2 * mt],     biasC[2 * mt]);
            Dn[g][mt][1] = fmaf(xv1, wihC[2 * mt],     biasC[2 * mt]);
            Dn[g][mt][2] = fmaf(xv0, wihC[2 * mt + 1], biasC[2 * mt + 1]);
            Dn[g][mt][3] = fmaf(xv1, wihC[2 * mt + 1], biasC[2 * mt + 1]);
        }
    }

    float c0[NG], c1[NG], h0[NG], h1[NG];
#pragma unroll
    for (int g = 0; g < NG; g++) { c0[g] = c1[g] = h0[g] = h1[g] = 0.f; }

    __syncthreads();

#pragma unroll 1
    for (int t = 0; t < T_LEN; t++) {
        // ---- single LDS.128 per group ----
        uint4 v[NG];
#pragma unroll
        for (int g = 0; g < NG; g++)
            v[g] = *(const uint4*)&bsm[t & 1][g][grp][8 * tig];

        // ---- split accumulators, 4 HMMA per group (independent chains) ----
        float Da[NG][2][4], Db[NG][2][4];
#pragma unroll
        for (int g = 0; g < NG; g++)
#pragma unroll
            for (int mt = 0; mt < 2; mt++)
#pragma unroll
                for (int j = 0; j < 4; j++) { Da[g][mt][j] = Dn[g][mt][j]; Db[g][mt][j] = 0.f; }

#pragma unroll
        for (int g = 0; g < NG; g++) {
            mma16816(Da[g][0], A[0][0], v[g].x, v[g].y);
            mma16816(Db[g][0], A[0][1], v[g].z, v[g].w);
            mma16816(Da[g][1], A[1][0], v[g].x, v[g].y);
            mma16816(Db[g][1], A[1][1], v[g].z, v[g].w);
        }

        // ---- activations + c/h update per group (fp32 tanh) ----
#pragma unroll
        for (int g = 0; g < NG; g++) {
            const float si0 = fmaf(0.5f, tanh_ap(Da[g][0][0] + Db[g][0][0]), 0.5f);
            const float si1 = fmaf(0.5f, tanh_ap(Da[g][0][1] + Db[g][0][1]), 0.5f);
            const float sf0 = fmaf(0.5f, tanh_ap(Da[g][0][2] + Db[g][0][2]), 0.5f);
            const float sf1 = fmaf(0.5f, tanh_ap(Da[g][0][3] + Db[g][0][3]), 0.5f);
            const float sg0 = tanh_ap(Da[g][1][0] + Db[g][1][0]);
            const float sg1 = tanh_ap(Da[g][1][1] + Db[g][1][1]);
            const float so0 = fmaf(0.5f, tanh_ap(Da[g][1][2] + Db[g][1][2]), 0.5f);
            const float so1 = fmaf(0.5f, tanh_ap(Da[g][1][3] + Db[g][1][3]), 0.5f);
            c0[g] = fmaf(sf0, c0[g], si0 * sg0);
            c1[g] = fmaf(sf1, c1[g], si1 * sg1);
            h0[g] = so0 * tanh_ap(c0[g]);
            h1[g] = so1 * tanh_ap(c1[g]);
            bsm[(t + 1) & 1][g][it0][pos_u] = __float2half(h0[g]);
            bsm[(t + 1) & 1][g][it1][pos_u] = __float2half(h1[g]);
        }

        // ---- epilogue (off-chain): seeds for t+1 ----
#pragma unroll
        for (int g = 0; g < NG; g++) {
            const float xv0n = __shfl_sync(0xffffffffu, xqn, 8 * g + it0);
            const float xv1n = __shfl_sync(0xffffffffu, xqn, 8 * g + it1);
#pragma unroll
            for (int mt = 0; mt < 2; mt++) {
                Dn[g][mt][0] = fmaf(xv0n, wihC[2 * mt],     biasC[2 * mt]);
                Dn[g][mt][1] = fmaf(xv1n, wihC[2 * mt],     biasC[2 * mt]);
                Dn[g][mt][2] = fmaf(xv0n, wihC[2 * mt + 1], biasC[2 * mt + 1]);
                Dn[g][mt][3] = fmaf(xv1n, wihC[2 * mt + 1], biasC[2 * mt + 1]);
            }
        }
        if (t + 2 < T_LEN) xp += stride;
        xqn = __ldg(xp);
        __syncthreads();
    }

#pragma unroll
    for (int g = 0; g < NG; g++) {
        g_hfinal[((b0 + 8 * g + it0) * E_N + e) * 64 + d * 32 + u] = h0[g];
        g_hfinal[((b0 + 8 * g + it1) * E_N + e) * 64 + d * 32 + u] = h1[g];
    }
}

// 296 CTAs = exactly 2 per SM (bid % 148 LUT placement):
//   bids 0..239   : eds 0..29, 8 CTAs each, 8 items (NG=1)
//   bids 240..287 : eds 30..37, 6 CTAs each, items 0..47 (NG=1)
//   bids 288..295 : eds 30..37, 1 CTA each, items 48..63 (NG=2)
__global__ void __launch_bounds__(128, 2)
lstm_kernel(const float* __restrict__ x,
            const float* __restrict__ w_ih,
            const float* __restrict__ w_hh,
            const float* __restrict__ b_ih,
            const float* __restrict__ b_hh)
{
    __shared__ __half bsm[2][2][8][32];
    const int bid = blockIdx.x;

    if (bid < 240) {
        run_lstm<1>(x, w_ih, w_hh, b_ih, b_hh, bid >> 3, (bid & 7) * 8,
                    threadIdx.x, bsm);
    } else if (bid < 288) {
        const int r = bid - 240;
        run_lstm<1>(x, w_ih, w_hh, b_ih, b_hh, 30 + r / 6, (r % 6) * 8,
                    threadIdx.x, bsm);
    } else {
        run_lstm<2>(x, w_ih, w_hh, b_ih, b_hh, 30 + (bid - 288), 48,
                    threadIdx.x, bsm);
    }
}

// Per-batch epilogue: per-electrode LayerNorm over 64 features, electrode mean, FC.
__global__ void __launch_bounds__(64)
head_kernel(const float* __restrict__ ln_gamma,
            const float* __restrict__ ln_beta,
            const float* __restrict__ fc_w,
            const float* __restrict__ fc_b,
            float* __restrict__ out)
{
    const int b = blockIdx.x;
    const int f = threadIdx.x;
    __shared__ float red[4];
    const float* hbp = g_hfinal + b * (E_N * 64);

    float pooled = 0.f;
    for (int e = 0; e < E_N; e++) {
        float v = hbp[e * 64 + f];
        float s = v, s2 = v * v;
#pragma unroll
        for (int off = 16; off; off >>= 1) {
            s  += __shfl_xor_sync(0xffffffffu, s,  off);
            s2 += __shfl_xor_sync(0xffffffffu, s2, off);
        }
        if ((f & 31) == 0) { red[(f >> 5) * 2] = s; red[(f >> 5) * 2 + 1] = s2; }
        __syncthreads();
        float S = red[0] + red[2], S2 = red[1] + red[3];
        __syncthreads();
        float mu  = S * (1.0f / 64.0f);
        float var = fmaf(-mu, mu, S2 * (1.0f / 64.0f));
        float nv  = (v - mu) * rsqrtf(var + 1e-5f);
        pooled += fmaf(nv, ln_gamma[e * 64 + f], ln_beta[e * 64 + f]);
    }
    pooled *= (1.0f / (float)E_N);

    float a = pooled * fc_w[f];
#pragma unroll
    for (int off = 16; off; off >>= 1) a += __shfl_xor_sync(0xffffffffu, a, off);
    if ((f & 31) == 0) red[f >> 5] = a;
    __syncthreads();
    if (f == 0) out[b] = red[0] + red[1] + fc_b[0];
}

extern "C" void kernel_launch(void* const* d_in, const int* in_sizes, int n_in,
                              void* d_out, int out_size) {
    const float* x        = (const float*)d_in[0];
    const float* w_ih     = (const float*)d_in[1];
    const float* w_hh     = (const float*)d_in[2];
    const float* b_ih     = (const float*)d_in[3];
    const float* b_hh     = (const float*)d_in[4];
    const float* ln_gamma = (const float*)d_in[5];
    const float* ln_beta  = (const float*)d_in[6];
    const float* fc_w     = (const float*)d_in[7];
    const float* fc_b     = (const float*)d_in[8];
    float* out = (float*)d_out;

    lstm_kernel<<<296, 128>>>(x, w_ih, w_hh, b_ih, b_hh);
    head_kernel<<<B_N, 64>>>(ln_gamma, ln_beta, fc_w, fc_b, out);
}

// round 13
// speedup vs baseline: 1.1555x; 1.1555x over previous
#include <cuda_runtime.h>
#include <cuda_fp16.h>

#define T_LEN 2048
#define E_N   19
#define B_N   64

typedef unsigned int u32;

// final hidden states: [b][e][dir*32+u]
__device__ float g_hfinal[B_N * E_N * 64];

__device__ __forceinline__ float tanh_ap(float x) {
    float r;
    asm("tanh.approx.f32 %0, %1;" : "=f"(r) : "f"(x));
    return r;
}

__device__ __forceinline__ u32 pack_hf2(float lo, float hi) {
    __half2 p;
    p.x = __float2half(lo);    // low 16 bits = lower k index
    p.y = __float2half(hi);
    return *(u32*)&p;
}

// D += A(16x16 fp16, row-major) * B(16x8 fp16, col-major), fp32 accumulate
__device__ __forceinline__ void mma16816(float d[4], const u32 a[4], u32 b0, u32 b1) {
    asm volatile(
        "mma.sync.aligned.m16n8k16.row.col.f32.f16.f16.f32 "
        "{%0,%1,%2,%3}, {%4,%5,%6,%7}, {%8,%9}, {%0,%1,%2,%3};"
        : "+f"(d[0]), "+f"(d[1]), "+f"(d[2]), "+f"(d[3])
        : "r"(a[0]), "r"(a[1]), "r"(a[2]), "r"(a[3]), "r"(b0), "r"(b1));
}

// One CTA = one (e,dir) x 8 items (HALF=false) or x 4 items (HALF=true).
// 4 warps; warp w owns units 8w..8w+7; M-rows permuted [i(8);f(8);g(8);o(8)]
// so each thread holds all four gates for (unit u, items 2tig/2tig+1).
// HALF: an 8-shfl redistribution gives each thread all 4 gates of
// (unit u, item tig) -> only 5 MUFU warp-instructions per step.
// h layout pos(u) = ((u&7)>>1)*8 + 2w + (u&1) -> single LDS.128;
// double-buffered bsm; seeds pipelined into previous epilogue via shfl.
template <bool HALF>
__device__ __forceinline__ void run_lstm(
    const float* __restrict__ x, const float* __restrict__ w_ih,
    const float* __restrict__ w_hh, const float* __restrict__ b_ih,
    const float* __restrict__ b_hh,
    int ed, int b0, int tid, __half (*bsm)[8][32])
{
    const int w    = tid >> 5;
    const int lane = tid & 31;
    const int grp  = lane >> 2;
    const int tig  = lane & 3;
    const int e    = ed >> 1;
    const int d    = ed & 1;

    const int u     = 8 * w + grp;
    const int pos_u = (grp >> 1) * 8 + 2 * w + (grp & 1);

    // ---- A fragments: m-tile mt rows = [gate 2mt units; gate 2mt+1 units] ----
    u32 A[2][2][4];
    {
        const float* Wp = w_hh + ed * 128 * 32;
#pragma unroll
        for (int mt = 0; mt < 2; mt++) {
            const int g0 = 2 * mt, g1 = 2 * mt + 1;
            const float C0 = (g0 == 2) ? 1.0f : 0.5f;
            const float C1 = (g1 == 2) ? 1.0f : 0.5f;
            const float* r0 = Wp + (g0 * 32 + u) * 32;
            const float* r1 = Wp + (g1 * 32 + u) * 32;
#pragma unroll
            for (int kt = 0; kt < 2; kt++) {
                const int kb = 16 * kt + 2 * tig;
                A[mt][kt][0] = pack_hf2(r0[kb] * C0,     r0[kb + 1] * C0);
                A[mt][kt][1] = pack_hf2(r1[kb] * C1,     r1[kb + 1] * C1);
                A[mt][kt][2] = pack_hf2(r0[kb + 8] * C0, r0[kb + 9] * C0);
                A[mt][kt][3] = pack_hf2(r1[kb + 8] * C1, r1[kb + 9] * C1);
            }
        }
    }

    // input weight / bias for unit u, gates 0..3 (activation scale folded)
    float wihC[4], biasC[4];
#pragma unroll
    for (int g = 0; g < 4; g++) {
        const float Cg = (g == 2) ? 1.0f : 0.5f;
        const int row = ed * 128 + g * 32 + u;
        wihC[g]  = Cg * w_ih[row];
        biasC[g] = Cg * (b_ih[row] + b_hh[row]);
    }

    // ---- zero both h buffers (h0 = 0): 2*8*32 halves = 256 u32 ----
    for (int i = tid; i < 256; i += 128) ((u32*)bsm)[i] = 0u;

    // ---- x pipeline: lane owns item lane&7 (full) / lane&3 (half) ----
    const int tstart = d ? (T_LEN - 1) : 0;
    const int stride = d ? -E_N : E_N;
    const int myitem = HALF ? (lane & 3) : (lane & 7);
    const float* xp = x + ((long long)(b0 + myitem) * T_LEN + tstart) * E_N + e;
    float xq  = __ldg(xp);
    xp += stride;
    float xqn = __ldg(xp);

    const int it0 = 2 * tig, it1 = 2 * tig + 1;

    // seeds for t=0 (MMA column layout; half: cols>=4 are dups, unused)
    float Dn[2][4];
    {
        const float xv0 = __shfl_sync(0xffffffffu, xq, it0);
        const float xv1 = __shfl_sync(0xffffffffu, xq, it1);
#pragma unroll
        for (int mt = 0; mt < 2; mt++) {
            Dn[mt][0] = fmaf(xv0, wihC[2 * mt],     biasC[2 * mt]);
            Dn[mt][1] = fmaf(xv1, wihC[2 * mt],     biasC[2 * mt]);
            Dn[mt][2] = fmaf(xv0, wihC[2 * mt + 1], biasC[2 * mt + 1]);
            Dn[mt][3] = fmaf(xv1, wihC[2 * mt + 1], biasC[2 * mt + 1]);
        }
    }

    float c0 = 0.f, c1 = 0.f, h0 = 0.f, h1 = 0.f;

    __syncthreads();

#pragma unroll 1
    for (int t = 0; t < T_LEN; t++) {
        // ---- single LDS.128: thread's 4 B-frag words are contiguous ----
        const uint4 v = *(const uint4*)&bsm[t & 1][grp][8 * tig];

        // ---- split accumulators: Da = seed + ktile0, Db = 0 + ktile1 ----
        float Da[2][4], Db[2][4];
#pragma unroll
        for (int mt = 0; mt < 2; mt++)
#pragma unroll
            for (int j = 0; j < 4; j++) { Da[mt][j] = Dn[mt][j]; Db[mt][j] = 0.f; }

        mma16816(Da[0], A[0][0], v.x, v.y);
        mma16816(Db[0], A[0][1], v.z, v.w);
        mma16816(Da[1], A[1][0], v.x, v.y);
        mma16816(Db[1], A[1][1], v.z, v.w);

        if (!HALF) {
            // ---- full path (identical to the 398us kernel) ----
            const float si0 = fmaf(0.5f, tanh_ap(Da[0][0] + Db[0][0]), 0.5f);
            const float si1 = fmaf(0.5f, tanh_ap(Da[0][1] + Db[0][1]), 0.5f);
            const float sf0 = fmaf(0.5f, tanh_ap(Da[0][2] + Db[0][2]), 0.5f);
            const float sf1 = fmaf(0.5f, tanh_ap(Da[0][3] + Db[0][3]), 0.5f);
            const float sg0 = tanh_ap(Da[1][0] + Db[1][0]);
            const float sg1 = tanh_ap(Da[1][1] + Db[1][1]);
            const float so0 = fmaf(0.5f, tanh_ap(Da[1][2] + Db[1][2]), 0.5f);
            const float so1 = fmaf(0.5f, tanh_ap(Da[1][3] + Db[1][3]), 0.5f);
            c0 = fmaf(sf0, c0, si0 * sg0);
            c1 = fmaf(sf1, c1, si1 * sg1);
            h0 = so0 * tanh_ap(c0);
            h1 = so1 * tanh_ap(c1);
            bsm[(t + 1) & 1][it0][pos_u] = __float2half(h0);
            bsm[(t + 1) & 1][it1][pos_u] = __float2half(h1);
        } else {
            // ---- half path: redistribute gates so thread owns (u, item=tig) ----
            float Dm[2][4];
#pragma unroll
            for (int mt = 0; mt < 2; mt++)
#pragma unroll
                for (int j = 0; j < 4; j++) Dm[mt][j] = Da[mt][j] + Db[mt][j];

            const int src = grp * 4 + (tig >> 1);
            const float gia = __shfl_sync(0xffffffffu, Dm[0][0], src);
            const float gib = __shfl_sync(0xffffffffu, Dm[0][1], src);
            const float gfa = __shfl_sync(0xffffffffu, Dm[0][2], src);
            const float gfb = __shfl_sync(0xffffffffu, Dm[0][3], src);
            const float gga = __shfl_sync(0xffffffffu, Dm[1][0], src);
            const float ggb = __shfl_sync(0xffffffffu, Dm[1][1], src);
            const float goa = __shfl_sync(0xffffffffu, Dm[1][2], src);
            const float gob = __shfl_sync(0xffffffffu, Dm[1][3], src);
            const bool odd = (tig & 1);
            const float gi = odd ? gib : gia;
            const float gf = odd ? gfb : gfa;
            const float gg = odd ? ggb : gga;
            const float go = odd ? gob : goa;

            const float si = fmaf(0.5f, tanh_ap(gi), 0.5f);
            const float sf = fmaf(0.5f, tanh_ap(gf), 0.5f);
            const float sg = tanh_ap(gg);
            const float so = fmaf(0.5f, tanh_ap(go), 0.5f);
            c0 = fmaf(sf, c0, si * sg);
            h0 = so * tanh_ap(c0);
            bsm[(t + 1) & 1][tig][pos_u] = __float2half(h0);   // rows 4-7 stay 0
        }

        // ---- epilogue (off-chain): seeds for t+1 ----
        {
            const float xv0n = __shfl_sync(0xffffffffu, xqn, it0);
            const float xv1n = __shfl_sync(0xffffffffu, xqn, it1);
#pragma unroll
            for (int mt = 0; mt < 2; mt++) {
                Dn[mt][0] = fmaf(xv0n, wihC[2 * mt],     biasC[2 * mt]);
                Dn[mt][1] = fmaf(xv1n, wihC[2 * mt],     biasC[2 * mt]);
                Dn[mt][2] = fmaf(xv0n, wihC[2 * mt + 1], biasC[2 * mt + 1]);
                Dn[mt][3] = fmaf(xv1n, wihC[2 * mt + 1], biasC[2 * mt + 1]);
            }
            if (t + 2 < T_LEN) xp += stride;
            xqn = __ldg(xp);
        }
        __syncthreads();
    }

    if (!HALF) {
        g_hfinal[((b0 + it0) * E_N + e) * 64 + d * 32 + u] = h0;
        g_hfinal[((b0 + it1) * E_N + e) * 64 + d * 32 + u] = h1;
    } else {
        g_hfinal[((b0 + tig) * E_N + e) * 64 + d * 32 + u] = h0;
    }
}

// 312 CTAs: 296 full + 16 half. Placement LUT[bid%148]: the 16 third-wave
// CTAs (bids 296..311 -> 16 distinct SMs) are HALF units -> those SMs carry
// 2.5 work units; all others exactly 2.0 (vs 304-grid's 8 SMs at 3.0).
//   bids 0..239   : eds 0..29, groups 0..7 (full, 8 items)
//   bids 240..295 : eds 30..37, groups 0..6 (full)
//   bids 296..311 : eds 30..37, group 7 split into items 56-59 / 60-63 (half)
__global__ void __launch_bounds__(128, 3)
lstm_kernel(const float* __restrict__ x,
            const float* __restrict__ w_ih,
            const float* __restrict__ w_hh,
            const float* __restrict__ b_ih,
            const float* __restrict__ b_hh)
{
    __shared__ __half bsm[2][8][32];
    const int bid = blockIdx.x;

    if (bid < 240) {
        run_lstm<false>(x, w_ih, w_hh, b_ih, b_hh, bid >> 3, (bid & 7) * 8,
                        threadIdx.x, bsm);
    } else if (bid < 296) {
        const int r = bid - 240;
        run_lstm<false>(x, w_ih, w_hh, b_ih, b_hh, 30 + r / 7, (r % 7) * 8,
                        threadIdx.x, bsm);
    } else {
        const int j = bid - 296;
        run_lstm<true>(x, w_ih, w_hh, b_ih, b_hh, 30 + (j >> 1),
                       56 + (j & 1) * 4, threadIdx.x, bsm);
    }
}

// Per-batch epilogue: per-electrode LayerNorm over 64 features, electrode mean, FC.
__global__ void __launch_bounds__(64)
head_kernel(const float* __restrict__ ln_gamma,
            const float* __restrict__ ln_beta,
            const float* __restrict__ fc_w,
            const float* __restrict__ fc_b,
            float* __restrict__ out)
{
    const int b = blockIdx.x;
    const int f = threadIdx.x;
    __shared__ float red[4];
    const float* hbp = g_hfinal + b * (E_N * 64);

    float pooled = 0.f;
    for (int e = 0; e < E_N; e++) {
        float v = hbp[e * 64 + f];
        float s = v, s2 = v * v;
#pragma unroll
        for (int off = 16; off; off >>= 1) {
            s  += __shfl_xor_sync(0xffffffffu, s,  off);
            s2 += __shfl_xor_sync(0xffffffffu, s2, off);
        }
        if ((f & 31) == 0) { red[(f >> 5) * 2] = s; red[(f >> 5) * 2 + 1] = s2; }
        __syncthreads();
        float S = red[0] + red[2], S2 = red[1] + red[3];
        __syncthreads();
        float mu  = S * (1.0f / 64.0f);
        float var = fmaf(-mu, mu, S2 * (1.0f / 64.0f));
        float nv  = (v - mu) * rsqrtf(var + 1e-5f);
        pooled += fmaf(nv, ln_gamma[e * 64 + f], ln_beta[e * 64 + f]);
    }
    pooled *= (1.0f / (float)E_N);

    float a = pooled * fc_w[f];
#pragma unroll
    for (int off = 16; off; off >>= 1) a += __shfl_xor_sync(0xffffffffu, a, off);
    if ((f & 31) == 0) red[f >> 5] = a;
    __syncthreads();
    if (f == 0) out[b] = red[0] + red[1] + fc_b[0];
}

extern "C" void kernel_launch(void* const* d_in, const int* in_sizes, int n_in,
                              void* d_out, int out_size) {
    const float* x        = (const float*)d_in[0];
    const float* w_ih     = (const float*)d_in[1];
    const float* w_hh     = (const float*)d_in[2];
    const float* b_ih     = (const float*)d_in[3];
    const float* b_hh     = (const float*)d_in[4];
    const float* ln_gamma = (const float*)d_in[5];
    const float* ln_beta  = (const float*)d_in[6];
    const float* fc_w     = (const float*)d_in[7];
    const float* fc_b     = (const float*)d_in[8];
    float* out = (float*)d_out;

    lstm_kernel<<<312, 128>>>(x, w_ih, w_hh, b_ih, b_hh);
    head_kernel<<<B_N, 64>>>(ln_gamma, ln_beta, fc_w, fc_b, out);
}

// round 14
// speedup vs baseline: 1.2410x; 1.0740x over previous
#include <cuda_runtime.h>
#include <cuda_fp16.h>

#define T_LEN 2048
#define E_N   19
#define B_N   64

typedef unsigned int u32;

// final hidden states: [b][e][dir*32+u]
__device__ float g_hfinal[B_N * E_N * 64];

__device__ __forceinline__ float tanh_ap(float x) {
    float r;
    asm("tanh.approx.f32 %0, %1;" : "=f"(r) : "f"(x));
    return r;
}
// pack two f32 into f16x2: lo half = first arg, hi half = second
__device__ __forceinline__ __half2 pack_f16x2(float lo, float hi) {
    u32 r;
    asm("cvt.rn.f16x2.f32 %0, %1, %2;" : "=r"(r) : "f"(hi), "f"(lo));
    return *(__half2*)&r;
}
// packed tanh: one MUFU for two values
__device__ __forceinline__ __half2 tanh_h2(__half2 a) {
    u32 r;
    asm("tanh.approx.f16x2 %0, %1;" : "=r"(r) : "r"(*(u32*)&a));
    return *(__half2*)&r;
}
__device__ __forceinline__ u32 pack_hf2(float lo, float hi) {
    __half2 p;
    p.x = __float2half(lo);
    p.y = __float2half(hi);
    return *(u32*)&p;
}

// D += A(16x16 fp16, row-major) * B(16x8 fp16, col-major), fp32 accumulate
__device__ __forceinline__ void mma16816(float d[4], const u32 a[4], u32 b0, u32 b1) {
    asm volatile(
        "mma.sync.aligned.m16n8k16.row.col.f32.f16.f16.f32 "
        "{%0,%1,%2,%3}, {%4,%5,%6,%7}, {%8,%9}, {%0,%1,%2,%3};"
        : "+f"(d[0]), "+f"(d[1]), "+f"(d[2]), "+f"(d[3])
        : "r"(a[0]), "r"(a[1]), "r"(a[2]), "r"(a[3]), "r"(b0), "r"(b1));
}

// One CTA = one (e,dir) x 8 batch items, 4 warps (uniform 304-CTA grid).
// Warp w owns units 8w..8w+7; M-rows permuted [i(8);f(8);g(8);o(8)] so each
// thread holds all four gates for (unit u, items it0/it1) after the MMA.
// Per-step budget cuts vs the 398us kernel:
//   - gate activations via tanh.approx.f16x2 (4 MUFU, was 8); cell tanh fp32
//   - seeds (x*w_ih + bias) as 4 HFMA2 in the epilogue, added post-MMA via
//     HADD2 -> deletes 8 seed FFMA + 8 merge FADD (depth-2 chained HMMA)
// h layout pos(u) = ((u&7)>>1)*8 + 2w + (u&1) -> single LDS.128;
// double-buffered bsm; x pipelined via shfl.
__global__ void __launch_bounds__(128)
lstm_kernel(const float* __restrict__ x,      // [B, T, E]
            const float* __restrict__ w_ih,   // [E, 2, 128]
            const float* __restrict__ w_hh,   // [E, 2, 128, 32]
            const float* __restrict__ b_ih,   // [E, 2, 128]
            const float* __restrict__ b_hh)   // [E, 2, 128]
{
    __shared__ __half bsm[2][8][32];   // [buf][item][pos(u)] fp16 h, 64B rows

    const int tid  = threadIdx.x;
    const int w    = tid >> 5;
    const int lane = tid & 31;
    const int grp  = lane >> 2;
    const int tig  = lane & 3;

    const int ed = blockIdx.x >> 3;
    const int b0 = (blockIdx.x & 7) * 8;
    const int e  = ed >> 1;
    const int d  = ed & 1;

    const int u     = 8 * w + grp;
    const int pos_u = (grp >> 1) * 8 + 2 * w + (grp & 1);

    // ---- A fragments: m-tile mt rows = [gate 2mt units; gate 2mt+1 units] ----
    u32 A[2][2][4];
    {
        const float* Wp = w_hh + ed * 128 * 32;
#pragma unroll
        for (int mt = 0; mt < 2; mt++) {
            const int g0 = 2 * mt, g1 = 2 * mt + 1;
            const float C0 = (g0 == 2) ? 1.0f : 0.5f;
            const float C1 = (g1 == 2) ? 1.0f : 0.5f;
            const float* r0 = Wp + (g0 * 32 + u) * 32;
            const float* r1 = Wp + (g1 * 32 + u) * 32;
#pragma unroll
            for (int kt = 0; kt < 2; kt++) {
                const int kb = 16 * kt + 2 * tig;
                A[mt][kt][0] = pack_hf2(r0[kb] * C0,     r0[kb + 1] * C0);
                A[mt][kt][1] = pack_hf2(r1[kb] * C1,     r1[kb + 1] * C1);
                A[mt][kt][2] = pack_hf2(r0[kb + 8] * C0, r0[kb + 9] * C0);
                A[mt][kt][3] = pack_hf2(r1[kb + 8] * C1, r1[kb + 9] * C1);
            }
        }
    }

    // input weight / bias (activation scale folded), duplicated into half2
    __half2 wih2[4], bias2[4];
#pragma unroll
    for (int g = 0; g < 4; g++) {
        const float Cg = (g == 2) ? 1.0f : 0.5f;
        const int row = ed * 128 + g * 32 + u;
        const float wv = Cg * w_ih[row];
        const float bv = Cg * (b_ih[row] + b_hh[row]);
        wih2[g]  = __floats2half2_rn(wv, wv);
        bias2[g] = __floats2half2_rn(bv, bv);
    }

    // ---- zero both h buffers (h0 = 0): 2*8*32 halves = 256 u32 ----
    for (int i = tid; i < 256; i += 128) ((u32*)bsm)[i] = 0u;

    // ---- x pipeline: lane owns item lane&7 ----
    const int tstart = d ? (T_LEN - 1) : 0;
    const int stride = d ? -E_N : E_N;
    const float* xp = x + ((long long)(b0 + (lane & 7)) * T_LEN + tstart) * E_N + e;
    float xq  = __ldg(xp);
    xp += stride;
    float xqn = __ldg(xp);

    const int it0 = 2 * tig, it1 = 2 * tig + 1;
    const __half2 h05 = __floats2half2_rn(0.5f, 0.5f);

    // seeds for t=0 (half2: lo=it0, hi=it1)
    __half2 seed[4];
    {
        const float xv0 = __shfl_sync(0xffffffffu, xq, it0);
        const float xv1 = __shfl_sync(0xffffffffu, xq, it1);
        const __half2 xh2 = pack_f16x2(xv0, xv1);
#pragma unroll
        for (int g = 0; g < 4; g++) seed[g] = __hfma2(xh2, wih2[g], bias2[g]);
    }

    float c0 = 0.f, c1 = 0.f, h0 = 0.f, h1 = 0.f;

    __syncthreads();

#pragma unroll 1
    for (int t = 0; t < T_LEN; t++) {
        // ---- single LDS.128: thread's 4 B-frag words are contiguous ----
        const uint4 v = *(const uint4*)&bsm[t & 1][grp][8 * tig];

        // ---- 4 HMMA, depth-2 chains (no merge FADD needed) ----
        float D[2][4];
#pragma unroll
        for (int mt = 0; mt < 2; mt++) {
            D[mt][0] = 0.f; D[mt][1] = 0.f; D[mt][2] = 0.f; D[mt][3] = 0.f;
            mma16816(D[mt], A[mt][0], v.x, v.y);
            mma16816(D[mt], A[mt][1], v.z, v.w);
        }

        // ---- pack gates, add seeds (fp16), packed tanh (4 MUFU) ----
        const __half2 pre_i = __hadd2(pack_f16x2(D[0][0], D[0][1]), seed[0]);
        const __half2 pre_f = __hadd2(pack_f16x2(D[0][2], D[0][3]), seed[1]);
        const __half2 pre_g = __hadd2(pack_f16x2(D[1][0], D[1][1]), seed[2]);
        const __half2 pre_o = __hadd2(pack_f16x2(D[1][2], D[1][3]), seed[3]);
        const __half2 ti = tanh_h2(pre_i);
        const __half2 tf = tanh_h2(pre_f);
        const __half2 tg = tanh_h2(pre_g);
        const __half2 to = tanh_h2(pre_o);
        const __half2 si = __hfma2(ti, h05, h05);
        const __half2 sf = __hfma2(tf, h05, h05);
        const __half2 so = __hfma2(to, h05, h05);
        const __half2 ig = __hmul2(si, tg);

        // ---- c update + cell tanh in fp32 (precision-critical) ----
        const float2 sff = __half22float2(sf);
        const float2 igf = __half22float2(ig);
        c0 = fmaf(sff.x, c0, igf.x);
        c1 = fmaf(sff.y, c1, igf.y);
        const float2 sof = __half22float2(so);
        h0 = sof.x * tanh_ap(c0);
        h1 = sof.y * tanh_ap(c1);
        bsm[(t + 1) & 1][it0][pos_u] = __float2half(h0);
        bsm[(t + 1) & 1][it1][pos_u] = __float2half(h1);

        // ---- epilogue (off-chain): seeds for t+1 ----
        {
            const float xv0n = __shfl_sync(0xffffffffu, xqn, it0);
            const float xv1n = __shfl_sync(0xffffffffu, xqn, it1);
            const __half2 xh2 = pack_f16x2(xv0n, xv1n);
#pragma unroll
            for (int g = 0; g < 4; g++) seed[g] = __hfma2(xh2, wih2[g], bias2[g]);
            if (t + 2 < T_LEN) xp += stride;
            xqn = __ldg(xp);
        }
        __syncthreads();
    }

    g_hfinal[((b0 + it0) * E_N + e) * 64 + d * 32 + u] = h0;
    g_hfinal[((b0 + it1) * E_N + e) * 64 + d * 32 + u] = h1;
}

// Per-batch epilogue: per-electrode LayerNorm over 64 features, electrode mean, FC.
__global__ void __launch_bounds__(64)
head_kernel(const float* __restrict__ ln_gamma,
            const float* __restrict__ ln_beta,
            const float* __restrict__ fc_w,
            const float* __restrict__ fc_b,
            float* __restrict__ out)
{
    const int b = blockIdx.x;
    const int f = threadIdx.x;
    __shared__ float red[4];
    const float* hbp = g_hfinal + b * (E_N * 64);

    float pooled = 0.f;
    for (int e = 0; e < E_N; e++) {
        float v = hbp[e * 64 + f];
        float s = v, s2 = v * v;
#pragma unroll
        for (int off = 16; off; off >>= 1) {
            s  += __shfl_xor_sync(0xffffffffu, s,  off);
            s2 += __shfl_xor_sync(0xffffffffu, s2, off);
        }
        if ((f & 31) == 0) { red[(f >> 5) * 2] = s; red[(f >> 5) * 2 + 1] = s2; }
        __syncthreads();
        float S = red[0] + red[2], S2 = red[1] + red[3];
        __syncthreads();
        float mu  = S * (1.0f / 64.0f);
        float var = fmaf(-mu, mu, S2 * (1.0f / 64.0f));
        float nv  = (v - mu) * rsqrtf(var + 1e-5f);
        pooled += fmaf(nv, ln_gamma[e * 64 + f], ln_beta[e * 64 + f]);
    }
    pooled *= (1.0f / (float)E_N);

    float a = pooled * fc_w[f];
#pragma unroll
    for (int off = 16; off; off >>= 1) a += __shfl_xor_sync(0xffffffffu, a, off);
    if ((f & 31) == 0) red[f >> 5] = a;
    __syncthreads();
    if (f == 0) out[b] = red[0] + red[1] + fc_b[0];
}

extern "C" void kernel_launch(void* const* d_in, const int* in_sizes, int n_in,
                              void* d_out, int out_size) {
    const float* x        = (const float*)d_in[0];
    const float* w_ih     = (const float*)d_in[1];
    const float* w_hh     = (const float*)d_in[2];
    const float* b_ih     = (const float*)d_in[3];
    const float* b_hh     = (const float*)d_in[4];
    const float* ln_gamma = (const float*)d_in[5];
    const float* ln_beta  = (const float*)d_in[6];
    const float* fc_w     = (const float*)d_in[7];
    const float* fc_b     = (const float*)d_in[8];
    float* out = (float*)d_out;

    lstm_kernel<<<E_N * 2 * 8, 128>>>(x, w_ih, w_hh, b_ih, b_hh);
    head_kernel<<<B_N, 64>>>(ln_gamma, ln_beta, fc_w, fc_b, out);
}

// round 15
// speedup vs baseline: 1.2861x; 1.0363x over previous
#include <cuda_runtime.h>
#include <cuda_fp16.h>

#define T_LEN 2048
#define E_N   19
#define B_N   64

typedef unsigned int u32;

// final hidden states: [b][e][dir*32+u]
__device__ float g_hfinal[B_N * E_N * 64];

__device__ __forceinline__ float tanh_ap(float x) {
    float r;
    asm("tanh.approx.f32 %0, %1;" : "=f"(r) : "f"(x));
    return r;
}
// packed tanh: one MUFU for two values
__device__ __forceinline__ u32 tanh_h2(u32 a) {
    u32 r;
    asm("tanh.approx.f16x2 %0, %1;" : "=r"(r) : "r"(a));
    return r;
}
__device__ __forceinline__ u32 pack_hf2(float lo, float hi) {
    __half2 p;
    p.x = __float2half(lo);
    p.y = __float2half(hi);
    return *(u32*)&p;
}
// pack two f32 into f16x2
__device__ __forceinline__ u32 packcvt(float lo, float hi) {
    u32 r;
    asm("cvt.rn.f16x2.f32 %0, %1, %2;" : "=r"(r) : "f"(hi), "f"(lo));
    return r;
}

// fp16-accumulating HMMA: D(half2 x2) = A(16x16 f16) * B(16x8 f16) + D.
// Thread (grp,tig): d0 = (row grp, cols 2tig/2tig+1), d1 = (row grp+8, same cols)
// -> with gate-paired row permutation, d0/d1 are the two gates' (it0,it1) pairs.
__device__ __forceinline__ void mma16816_f16(u32& d0, u32& d1, const u32 a[4],
                                             u32 b0, u32 b1) {
    asm volatile(
        "mma.sync.aligned.m16n8k16.row.col.f16.f16.f16.f16 "
        "{%0,%1}, {%2,%3,%4,%5}, {%6,%7}, {%0,%1};"
        : "+r"(d0), "+r"(d1)
        : "r"(a[0]), "r"(a[1]), "r"(a[2]), "r"(a[3]), "r"(b0), "r"(b1));
}

// One CTA = one (e,dir) x 8 batch items, 4 warps; 304 CTAs = exactly
// 2 CTAs/SM on GB300's 152 SMs (uniform).
// Warp w owns units 8w..8w+7; M-rows permuted [i(8);f(8);g(8);o(8)].
// fp16-accum HMMA with seeds as the C operand: D = A1*B1 + (A0*B0 + seed);
// D arrives as packed (it0,it1) half2 per gate -> tanh.approx.f16x2 directly
// (4 MUFU). Cell path (c accumulate + cell tanh) stays fp32.
// h layout pos(u) = ((u&7)>>1)*8 + 2w + (u&1) -> single LDS.128;
// double-buffered bsm; x pipelined via shfl; seeds HFMA2 in the epilogue.
__global__ void __launch_bounds__(128)
lstm_kernel(const float* __restrict__ x,      // [B, T, E]
            const float* __restrict__ w_ih,   // [E, 2, 128]
            const float* __restrict__ w_hh,   // [E, 2, 128, 32]
            const float* __restrict__ b_ih,   // [E, 2, 128]
            const float* __restrict__ b_hh)   // [E, 2, 128]
{
    __shared__ __half bsm[2][8][32];   // [buf][item][pos(u)] fp16 h, 64B rows

    const int tid  = threadIdx.x;
    const int w    = tid >> 5;
    const int lane = tid & 31;
    const int grp  = lane >> 2;
    const int tig  = lane & 3;

    const int ed = blockIdx.x >> 3;
    const int b0 = (blockIdx.x & 7) * 8;
    const int e  = ed >> 1;
    const int d  = ed & 1;

    const int u     = 8 * w + grp;
    const int pos_u = (grp >> 1) * 8 + 2 * w + (grp & 1);

    // ---- A fragments: m-tile mt rows = [gate 2mt units; gate 2mt+1 units] ----
    u32 A[2][2][4];
    {
        const float* Wp = w_hh + ed * 128 * 32;
#pragma unroll
        for (int mt = 0; mt < 2; mt++) {
            const int g0 = 2 * mt, g1 = 2 * mt + 1;
            const float C0 = (g0 == 2) ? 1.0f : 0.5f;
            const float C1 = (g1 == 2) ? 1.0f : 0.5f;
            const float* r0 = Wp + (g0 * 32 + u) * 32;
            const float* r1 = Wp + (g1 * 32 + u) * 32;
#pragma unroll
            for (int kt = 0; kt < 2; kt++) {
                const int kb = 16 * kt + 2 * tig;
                A[mt][kt][0] = pack_hf2(r0[kb] * C0,     r0[kb + 1] * C0);
                A[mt][kt][1] = pack_hf2(r1[kb] * C1,     r1[kb + 1] * C1);
                A[mt][kt][2] = pack_hf2(r0[kb + 8] * C0, r0[kb + 9] * C0);
                A[mt][kt][3] = pack_hf2(r1[kb + 8] * C1, r1[kb + 9] * C1);
            }
        }
    }

    // input weight / bias (activation scale folded), duplicated into half2
    __half2 wih2[4], bias2[4];
#pragma unroll
    for (int g = 0; g < 4; g++) {
        const float Cg = (g == 2) ? 1.0f : 0.5f;
        const int row = ed * 128 + g * 32 + u;
        const float wv = Cg * w_ih[row];
        const float bv = Cg * (b_ih[row] + b_hh[row]);
        wih2[g]  = __floats2half2_rn(wv, wv);
        bias2[g] = __floats2half2_rn(bv, bv);
    }

    // ---- zero both h buffers (h0 = 0): 2*8*32 halves = 256 u32 ----
    for (int i = tid; i < 256; i += 128) ((u32*)bsm)[i] = 0u;

    // ---- x pipeline: lane owns item lane&7 ----
    const int tstart = d ? (T_LEN - 1) : 0;
    const int stride = d ? -E_N : E_N;
    const float* xp = x + ((long long)(b0 + (lane & 7)) * T_LEN + tstart) * E_N + e;
    float xq  = __ldg(xp);
    xp += stride;
    float xqn = __ldg(xp);

    const int it0 = 2 * tig, it1 = 2 * tig + 1;
    const __half2 h05 = __floats2half2_rn(0.5f, 0.5f);

    // seeds for t=0 (half2: lo=it0, hi=it1), one per gate
    __half2 seed[4];
    {
        const float xv0 = __shfl_sync(0xffffffffu, xq, it0);
        const float xv1 = __shfl_sync(0xffffffffu, xq, it1);
        const u32 xu = packcvt(xv0, xv1);
        const __half2 xh2 = *(const __half2*)&xu;
#pragma unroll
        for (int g = 0; g < 4; g++) seed[g] = __hfma2(xh2, wih2[g], bias2[g]);
    }

    float c0 = 0.f, c1 = 0.f, h0 = 0.f, h1 = 0.f;

    __syncthreads();

#pragma unroll 1
    for (int t = 0; t < T_LEN; t++) {
        // ---- single LDS.128: thread's 4 B-frag words are contiguous ----
        const uint4 v = *(const uint4*)&bsm[t & 1][grp][8 * tig];

        // ---- 4 fp16-accum HMMA, seeds as C: D = A1*B1 + (A0*B0 + seed) ----
        u32 Di = *(const u32*)&seed[0];   // mt0 d0: i-gate (it0,it1)
        u32 Df = *(const u32*)&seed[1];   // mt0 d1: f-gate
        u32 Dg = *(const u32*)&seed[2];   // mt1 d0: g-gate
        u32 Do = *(const u32*)&seed[3];   // mt1 d1: o-gate
        mma16816_f16(Di, Df, A[0][0], v.x, v.y);
        mma16816_f16(Di, Df, A[0][1], v.z, v.w);
        mma16816_f16(Dg, Do, A[1][0], v.x, v.y);
        mma16816_f16(Dg, Do, A[1][1], v.z, v.w);

        // ---- packed gate activations (4 MUFU) ----
        const u32 tiu = tanh_h2(Di);
        const u32 tfu = tanh_h2(Df);
        const u32 tgu = tanh_h2(Dg);
        const u32 tou = tanh_h2(Do);
        const __half2 si = __hfma2(*(const __half2*)&tiu, h05, h05);
        const __half2 sf = __hfma2(*(const __half2*)&tfu, h05, h05);
        const __half2 so = __hfma2(*(const __half2*)&tou, h05, h05);
        const __half2 ig = __hmul2(si, *(const __half2*)&tgu);

        // ---- c update + cell tanh in fp32 (precision-critical) ----
        const float2 sff = __half22float2(sf);
        const float2 igf = __half22float2(ig);
        c0 = fmaf(sff.x, c0, igf.x);
        c1 = fmaf(sff.y, c1, igf.y);
        const float2 sof = __half22float2(so);
        h0 = sof.x * tanh_ap(c0);
        h1 = sof.y * tanh_ap(c1);
        bsm[(t + 1) & 1][it0][pos_u] = __float2half(h0);
        bsm[(t + 1) & 1][it1][pos_u] = __float2half(h1);

        // ---- epilogue (off-chain): seeds for t+1 ----
        {
            const float xv0n = __shfl_sync(0xffffffffu, xqn, it0);
            const float xv1n = __shfl_sync(0xffffffffu, xqn, it1);
            const u32 xu = packcvt(xv0n, xv1n);
            const __half2 xh2 = *(const __half2*)&xu;
#pragma unroll
            for (int g = 0; g < 4; g++) seed[g] = __hfma2(xh2, wih2[g], bias2[g]);
            if (t + 2 < T_LEN) xp += stride;
            xqn = __ldg(xp);
        }
        __syncthreads();
    }

    g_hfinal[((b0 + it0) * E_N + e) * 64 + d * 32 + u] = h0;
    g_hfinal[((b0 + it1) * E_N + e) * 64 + d * 32 + u] = h1;
}

// Per-batch epilogue: per-electrode LayerNorm over 64 features, electrode mean, FC.
__global__ void __launch_bounds__(64)
head_kernel(const float* __restrict__ ln_gamma,
            const float* __restrict__ ln_beta,
            const float* __restrict__ fc_w,
            const float* __restrict__ fc_b,
            float* __restrict__ out)
{
    const int b = blockIdx.x;
    const int f = threadIdx.x;
    __shared__ float red[4];
    const float* hbp = g_hfinal + b * (E_N * 64);

    float pooled = 0.f;
    for (int e = 0; e < E_N; e++) {
        float v = hbp[e * 64 + f];
        float s = v, s2 = v * v;
#pragma unroll
        for (int off = 16; off; off >>= 1) {
            s  += __shfl_xor_sync(0xffffffffu, s,  off);
            s2 += __shfl_xor_sync(0xffffffffu, s2, off);
        }
        if ((f & 31) == 0) { red[(f >> 5) * 2] = s; red[(f >> 5) * 2 + 1] = s2; }
        __syncthreads();
        float S = red[0] + red[2], S2 = red[1] + red[3];
        __syncthreads();
        float mu  = S * (1.0f / 64.0f);
        float var = fmaf(-mu, mu, S2 * (1.0f / 64.0f));
        float nv  = (v - mu) * rsqrtf(var + 1e-5f);
        pooled += fmaf(nv, ln_gamma[e * 64 + f], ln_beta[e * 64 + f]);
    }
    pooled *= (1.0f / (float)E_N);

    float a = pooled * fc_w[f];
#pragma unroll
    for (int off = 16; off; off >>= 1) a += __shfl_xor_sync(0xffffffffu, a, off);
    if ((f & 31) == 0) red[f >> 5] = a;
    __syncthreads();
    if (f == 0) out[b] = red[0] + red[1] + fc_b[0];
}

extern "C" void kernel_launch(void* const* d_in, const int* in_sizes, int n_in,
                              void* d_out, int out_size) {
    const float* x        = (const float*)d_in[0];
    const float* w_ih     = (const float*)d_in[1];
    const float* w_hh     = (const float*)d_in[2];
    const float* b_ih     = (const float*)d_in[3];
    const float* b_hh     = (const float*)d_in[4];
    const float* ln_gamma = (const float*)d_in[5];
    const float* ln_beta  = (const float*)d_in[6];
    const float* fc_w     = (const float*)d_in[7];
    const float* fc_b     = (const float*)d_in[8];
    float* out = (float*)d_out;

    lstm_kernel<<<E_N * 2 * 8, 128>>>(x, w_ih, w_hh, b_ih, b_hh);
    head_kernel<<<B_N, 64>>>(ln_gamma, ln_beta, fc_w, fc_b, out);
}